// round 1
// baseline (speedup 1.0000x reference)
#include <cuda_runtime.h>
#include <math.h>

// ---------------------------------------------------------------------------
// Scratch (single __device__ global array; no allocations anywhere)
// ---------------------------------------------------------------------------
#define C0_OFF   0u                       // 64*24*64*64 = 6291456
#define C1_OFF   6291456u                 // 64*24*32*32 = 1572864
#define C2_OFF   7864320u                 // 64*24*16*16 = 393216
#define C3_OFF   8257536u                 // 64*24*8*8   = 98304
#define HI_OFF   8355840u                 // 64*64*256   = 1048576
#define HJ_OFF   9404416u                 // 64*64*256   = 1048576
#define SP_OFF   10452992u                // 4096*256    = 1048576
#define SCRATCH_TOTAL 11501568u

__device__ float g_scratch[SCRATCH_TOTAL];

// ---------------------------------------------------------------------------
// Conv + BN + ReLU  (stride 2, pad 1, 3x3, HWIO weights, NCHW tensors)
// Block: one (n, 8x8 output tile); 192 threads = 24 co x 8 output rows.
// ---------------------------------------------------------------------------
template<int CIN, int CHUNK>
__global__ void __launch_bounds__(192) conv_bn_relu_kernel(
    const float* __restrict__ in, const float* __restrict__ w,
    const float* __restrict__ bns, const float* __restrict__ bnb,
    float* __restrict__ out, int Hin, int Hout, int tps)
{
    __shared__ float in_s[CHUNK * 289];      // CHUNK x 17 x 17
    __shared__ float w_s[9 * CHUNK * 24];    // (kh*3+kw) x ci x co

    int t   = threadIdx.x;
    int co  = t % 24;
    int ohl = t / 24;                        // 0..7 (output row in tile)
    int tiles = tps * tps;
    int n  = blockIdx.x / tiles;
    int tl = blockIdx.x % tiles;
    int oh0 = (tl / tps) * 8;
    int ow0 = (tl % tps) * 8;

    float acc[8];
#pragma unroll
    for (int i = 0; i < 8; i++) acc[i] = 0.f;

    for (int cc = 0; cc < CIN; cc += CHUNK) {
        __syncthreads();
        // load input tile chunk with zero padding
        for (int l = t; l < CHUNK * 289; l += 192) {
            int ci  = l / 289;
            int rem = l % 289;
            int r = rem / 17, c = rem % 17;
            int ih = oh0 * 2 - 1 + r;
            int iw = ow0 * 2 - 1 + c;
            float v = 0.f;
            if (ih >= 0 && ih < Hin && iw >= 0 && iw < Hin)
                v = in[((n * CIN + cc + ci) * Hin + ih) * Hin + iw];
            in_s[l] = v;
        }
        // load weight chunk
        for (int l = t; l < 9 * CHUNK * 24; l += 192) {
            int kk  = l / (CHUNK * 24);
            int rem = l % (CHUNK * 24);
            int ci = rem / 24, c2 = rem % 24;
            w_s[l] = w[(kk * CIN + cc + ci) * 24 + c2];
        }
        __syncthreads();

#pragma unroll
        for (int kh = 0; kh < 3; kh++)
#pragma unroll
            for (int kw = 0; kw < 3; kw++)
                for (int ci = 0; ci < CHUNK; ci++) {
                    float wv = w_s[(kh * 3 + kw) * CHUNK * 24 + ci * 24 + co];
                    const float* ir = &in_s[ci * 289 + (ohl * 2 + kh) * 17 + kw];
#pragma unroll
                    for (int o = 0; o < 8; o++)
                        acc[o] += wv * ir[o * 2];
                }
    }

    float sc = bns[co], bb = bnb[co];
#pragma unroll
    for (int o = 0; o < 8; o++) {
        float v = fmaxf(acc[o] * sc + bb, 0.f);
        out[((n * 24 + co) * Hout + oh0 + ohl) * Hout + ow0 + o] = v;
    }
}

// ---------------------------------------------------------------------------
// g layer 1: build x = [conv3 features, cx, cy], compute
//   hi'[n,p,o] = x[n,p]@W1a[:,o] + qst[n]@W1c[:,o] + b1[o]   (hq folded in)
//   hj [n,p,o] = x[n,p]@W1b[:,o]
// One block per n, 256 threads (one output column each).
// ---------------------------------------------------------------------------
__global__ void __launch_bounds__(256) g1_kernel(
    const float* __restrict__ c3, const float* __restrict__ qst,
    const float* __restrict__ gw1, const float* __restrict__ gb1,
    float* __restrict__ hi, float* __restrict__ hj)
{
    __shared__ float xs[64 * 26];
    __shared__ float qs[128];
    int n = blockIdx.x, t = threadIdx.x;

    for (int l = t; l < 64 * 26; l += 256) {
        int p = l / 26, c = l % 26;
        int h = p >> 3, w = p & 7;
        float v;
        if (c < 24)      v = c3[((n * 24 + c) * 8 + h) * 8 + w];
        else if (c == 24) v = -1.f + (2.f / 7.f) * (float)w;   // cx along W
        else              v = -1.f + (2.f / 7.f) * (float)h;   // cy along H
        xs[l] = v;
    }
    if (t < 128) qs[t] = qst[n * 128 + t];
    __syncthreads();

    int o = t;
    float wa[26], wb[26];
#pragma unroll
    for (int c = 0; c < 26; c++) {
        wa[c] = gw1[c * 256 + o];
        wb[c] = gw1[(26 + c) * 256 + o];
    }
    float hq = gb1[o];
    for (int k = 0; k < 128; k++) hq += qs[k] * gw1[(52 + k) * 256 + o];

    for (int p = 0; p < 64; p++) {
        float ai = hq, bj = 0.f;
#pragma unroll
        for (int c = 0; c < 26; c++) {
            float x = xs[p * 26 + c];
            ai += x * wa[c];
            bj += x * wb[c];
        }
        hi[(n * 64 + p) * 256 + o] = ai;
        hj[(n * 64 + p) * 256 + o] = bj;
    }
}

// ---------------------------------------------------------------------------
// Fused relation MLP. Block = (n, i): 64 pairs (i, j=0..63).
// h tiles live in smem feature-major: hT[feat][m], swizzled
//   hidx(f, m) = f*64 + ((m + (f & 60)) & 63)
// Each thread owns a [16 m x 4 o] register tile (64 fp32 accumulators).
// Layers: A->B (g2), B->A (g3), A->partials (g4), then deterministic
// per-block partial sums to global (reduced later).
// ---------------------------------------------------------------------------
template<bool LAST>
__device__ __forceinline__ void g_layer(
    const float* __restrict__ src, float* __restrict__ dst,
    const float* __restrict__ W, const float* __restrict__ B,
    int m0, int o0, int mt)
{
    float acc[16][4];
#pragma unroll
    for (int mm = 0; mm < 16; mm++)
#pragma unroll
        for (int oo = 0; oo < 4; oo++) acc[mm][oo] = 0.f;

#pragma unroll 2
    for (int k = 0; k < 256; k++) {
        float4 wv = *(const float4*)(W + (k << 8) + o0);
        const float* row = src + (k << 6);
        int sw = k & 60;
        float4 h0 = *(const float4*)(row + ((m0 +  0 + sw) & 63));
        float4 h1 = *(const float4*)(row + ((m0 +  4 + sw) & 63));
        float4 h2 = *(const float4*)(row + ((m0 +  8 + sw) & 63));
        float4 h3 = *(const float4*)(row + ((m0 + 12 + sw) & 63));
        float hv[16];
        hv[0]=h0.x; hv[1]=h0.y; hv[2]=h0.z; hv[3]=h0.w;
        hv[4]=h1.x; hv[5]=h1.y; hv[6]=h1.z; hv[7]=h1.w;
        hv[8]=h2.x; hv[9]=h2.y; hv[10]=h2.z; hv[11]=h2.w;
        hv[12]=h3.x; hv[13]=h3.y; hv[14]=h3.z; hv[15]=h3.w;
#pragma unroll
        for (int mm = 0; mm < 16; mm++) {
            float h = hv[mm];
            acc[mm][0] += h * wv.x;
            acc[mm][1] += h * wv.y;
            acc[mm][2] += h * wv.z;
            acc[mm][3] += h * wv.w;
        }
    }

    float4 bv = *(const float4*)(B + o0);
    float bb[4] = { bv.x, bv.y, bv.z, bv.w };

    if (!LAST) {
        int sw2 = o0 & 60;
#pragma unroll
        for (int oo = 0; oo < 4; oo++) {
            float* drow = dst + (o0 + oo) * 64;
#pragma unroll
            for (int q = 0; q < 4; q++) {
                float4 v;
                v.x = fmaxf(acc[4 * q + 0][oo] + bb[oo], 0.f);
                v.y = fmaxf(acc[4 * q + 1][oo] + bb[oo], 0.f);
                v.z = fmaxf(acc[4 * q + 2][oo] + bb[oo], 0.f);
                v.w = fmaxf(acc[4 * q + 3][oo] + bb[oo], 0.f);
                *(float4*)(drow + ((m0 + 4 * q + sw2) & 63)) = v;
            }
        }
    } else {
        // sum over this thread's 16 m values, write per-(mt) partials
        float4 p;
        float pv[4];
#pragma unroll
        for (int oo = 0; oo < 4; oo++) {
            float s = 0.f;
#pragma unroll
            for (int mm = 0; mm < 16; mm++)
                s += fmaxf(acc[mm][oo] + bb[oo], 0.f);
            pv[oo] = s;
        }
        p.x = pv[0]; p.y = pv[1]; p.z = pv[2]; p.w = pv[3];
        *(float4*)(dst + mt * 256 + o0) = p;
    }
}

__global__ void __launch_bounds__(256) rn_g_kernel(
    const float* __restrict__ hi, const float* __restrict__ hj,
    const float* __restrict__ w2, const float* __restrict__ b2,
    const float* __restrict__ w3, const float* __restrict__ b3,
    const float* __restrict__ w4, const float* __restrict__ b4,
    float* __restrict__ spart)
{
    extern __shared__ float sm[];
    float* hA = sm;
    float* hB = sm + 16384;

    int n = blockIdx.x >> 6, i = blockIdx.x & 63;
    int t = threadIdx.x;
    int mt = t >> 6, ot = t & 63;
    int m0 = mt << 4, o0 = ot << 2;

    // ----- layer 0: h0 = relu(hi'[n,i] + hj[n,m]) -----
    const float* hir = hi + ((n << 6) + i) * 256 + o0;
    float base[4] = { hir[0], hir[1], hir[2], hir[3] };
    const float* hjb = hj + ((size_t)(n << 6)) * 256;
    int sw2 = o0 & 60;
#pragma unroll
    for (int mm = 0; mm < 16; mm++) {
        int m = m0 + mm;
        const float* hjr = hjb + (m << 8) + o0;
#pragma unroll
        for (int oo = 0; oo < 4; oo++) {
            float v = fmaxf(base[oo] + hjr[oo], 0.f);
            hA[(o0 + oo) * 64 + ((m + sw2) & 63)] = v;
        }
    }
    __syncthreads();

    g_layer<false>(hA, hB, w2, b2, m0, o0, mt);
    __syncthreads();
    g_layer<false>(hB, hA, w3, b3, m0, o0, mt);
    __syncthreads();
    g_layer<true>(hA, hB, w4, b4, m0, o0, mt);   // partials into hB[mt*256+o]
    __syncthreads();

    float s = hB[t] + hB[256 + t] + hB[512 + t] + hB[768 + t];
    spart[(size_t)blockIdx.x * 256 + t] = s;
}

// ---------------------------------------------------------------------------
// Reduce partials over i, then f-MLP + classifier + log_softmax.
// One block per n, 256 threads.
// ---------------------------------------------------------------------------
__global__ void __launch_bounds__(256) f_kernel(
    const float* __restrict__ spart,
    const float* __restrict__ fw1, const float* __restrict__ fb1,
    const float* __restrict__ fw2, const float* __restrict__ fb2,
    const float* __restrict__ cw,  const float* __restrict__ cb,
    float* __restrict__ out)
{
    __shared__ float a[256], b[256];
    int n = blockIdx.x, t = threadIdx.x;

    const float* sp = spart + (size_t)(n << 6) * 256 + t;
    float v = 0.f;
    for (int i = 0; i < 64; i++) v += sp[i * 256];
    a[t] = v;
    __syncthreads();

    float acc = fb1[t];
    for (int k = 0; k < 256; k++) acc += a[k] * fw1[k * 256 + t];
    acc = fmaxf(acc, 0.f);
    b[t] = acc;
    __syncthreads();

    acc = fb2[t];
    for (int k = 0; k < 256; k++) acc += b[k] * fw2[k * 256 + t];
    acc = fmaxf(acc, 0.f);
    a[t] = acc;
    __syncthreads();

    if (t < 32) {
        float lg = cb[t];
        for (int k = 0; k < 256; k++) lg += a[k] * cw[k * 32 + t];
        float mx = lg;
#pragma unroll
        for (int off = 16; off; off >>= 1)
            mx = fmaxf(mx, __shfl_xor_sync(0xffffffffu, mx, off));
        float e = expf(lg - mx);
        float se = e;
#pragma unroll
        for (int off = 16; off; off >>= 1)
            se += __shfl_xor_sync(0xffffffffu, se, off);
        out[(n << 5) + t] = lg - mx - logf(se);
    }
}

// ---------------------------------------------------------------------------
// Launch
// ---------------------------------------------------------------------------
extern "C" void kernel_launch(void* const* d_in, const int* in_sizes, int n_in,
                              void* d_out, int out_size)
{
    const float* img  = (const float*)d_in[0];
    const float* qst  = (const float*)d_in[1];
    const float* cw0  = (const float*)d_in[2];
    const float* cw1  = (const float*)d_in[3];
    const float* cw2  = (const float*)d_in[4];
    const float* cw3  = (const float*)d_in[5];
    const float* bs0  = (const float*)d_in[6];
    const float* bb0  = (const float*)d_in[7];
    const float* bs1  = (const float*)d_in[8];
    const float* bb1  = (const float*)d_in[9];
    const float* bs2  = (const float*)d_in[10];
    const float* bb2  = (const float*)d_in[11];
    const float* bs3  = (const float*)d_in[12];
    const float* bb3  = (const float*)d_in[13];
    const float* gw1  = (const float*)d_in[14];
    const float* gb1  = (const float*)d_in[15];
    const float* gw2  = (const float*)d_in[16];
    const float* gb2  = (const float*)d_in[17];
    const float* gw3  = (const float*)d_in[18];
    const float* gb3  = (const float*)d_in[19];
    const float* gw4  = (const float*)d_in[20];
    const float* gb4  = (const float*)d_in[21];
    const float* fw1  = (const float*)d_in[22];
    const float* fb1  = (const float*)d_in[23];
    const float* fw2  = (const float*)d_in[24];
    const float* fb2  = (const float*)d_in[25];
    const float* clw  = (const float*)d_in[26];
    const float* clb  = (const float*)d_in[27];
    float* out = (float*)d_out;

    void* base_v = nullptr;
    cudaGetSymbolAddress(&base_v, g_scratch);
    float* base = (float*)base_v;
    float* c0 = base + C0_OFF;
    float* c1 = base + C1_OFF;
    float* c2 = base + C2_OFF;
    float* c3 = base + C3_OFF;
    float* hi = base + HI_OFF;
    float* hj = base + HJ_OFF;
    float* sp = base + SP_OFF;

    cudaFuncSetAttribute(rn_g_kernel,
                         cudaFuncAttributeMaxDynamicSharedMemorySize, 131072);

    conv_bn_relu_kernel<3, 3><<<4096, 192>>>(img, cw0, bs0, bb0, c0, 128, 64, 8);
    conv_bn_relu_kernel<24, 12><<<1024, 192>>>(c0, cw1, bs1, bb1, c1, 64, 32, 4);
    conv_bn_relu_kernel<24, 12><<<256, 192>>>(c1, cw2, bs2, bb2, c2, 32, 16, 2);
    conv_bn_relu_kernel<24, 12><<<64, 192>>>(c2, cw3, bs3, bb3, c3, 16, 8, 1);

    g1_kernel<<<64, 256>>>(c3, qst, gw1, gb1, hi, hj);

    rn_g_kernel<<<4096, 256, 131072>>>(hi, hj, gw2, gb2, gw3, gb3, gw4, gb4, sp);

    f_kernel<<<64, 256>>>(sp, fw1, fb1, fw2, fb2, clw, clb, out);
}

// round 3
// speedup vs baseline: 3.2515x; 3.2515x over previous
#include <cuda_runtime.h>
#include <cuda_bf16.h>
#include <math.h>
#include <cstdint>

// ---------------------------------------------------------------------------
// Scratch
// ---------------------------------------------------------------------------
#define C0_OFF   0u
#define C1_OFF   6291456u
#define C2_OFF   7864320u
#define C3_OFF   8257536u
#define HI_OFF   8355840u
#define HJ_OFF   9404416u
#define SP_OFF   10452992u                // 2048*256 floats used
#define WP_OFF   11501568u                // 196608 floats = 786KB weight blob
#define SCRATCH_TOTAL 11698176u

__device__ float g_scratch[SCRATCH_TOTAL];

// ---------------------------------------------------------------------------
// Helpers
// ---------------------------------------------------------------------------
__device__ __forceinline__ uint32_t smem_u32(const void* p) {
    uint32_t a;
    asm("{ .reg .u64 t; cvta.to.shared.u64 t, %1; cvt.u32.u64 %0, t; }" : "=r"(a) : "l"(p));
    return a;
}

__device__ __forceinline__ void mma_bf16(float& d0, float& d1, float& d2, float& d3,
                                         uint32_t a0, uint32_t a1, uint32_t a2, uint32_t a3,
                                         uint32_t b0, uint32_t b1) {
    asm volatile(
        "mma.sync.aligned.m16n8k16.row.col.f32.bf16.bf16.f32 "
        "{%0,%1,%2,%3},{%4,%5,%6,%7},{%8,%9},{%0,%1,%2,%3};"
        : "+f"(d0), "+f"(d1), "+f"(d2), "+f"(d3)
        : "r"(a0), "r"(a1), "r"(a2), "r"(a3), "r"(b0), "r"(b1));
}

// pack: low half = bf16(lo), high half = bf16(hi)
__device__ __forceinline__ uint32_t packbf(float lo, float hi) {
    uint32_t r;
    asm("cvt.rn.bf16x2.f32 %0, %1, %2;" : "=r"(r) : "f"(hi), "f"(lo));
    return r;
}
__device__ __forceinline__ float bfLO(uint32_t w) { return __uint_as_float(w << 16); }
__device__ __forceinline__ float bfHI(uint32_t w) { return __uint_as_float(w & 0xffff0000u); }

#define CP_ASYNC16(dst, src) \
    asm volatile("cp.async.cg.shared.global [%0], [%1], 16;" :: "r"(dst), "l"(src) : "memory")
#define CP_COMMIT() asm volatile("cp.async.commit_group;" ::: "memory")

// ---------------------------------------------------------------------------
// Conv + BN + ReLU (unchanged)
// ---------------------------------------------------------------------------
template<int CIN, int CHUNK>
__global__ void __launch_bounds__(192) conv_bn_relu_kernel(
    const float* __restrict__ in, const float* __restrict__ w,
    const float* __restrict__ bns, const float* __restrict__ bnb,
    float* __restrict__ out, int Hin, int Hout, int tps)
{
    __shared__ float in_s[CHUNK * 289];
    __shared__ float w_s[9 * CHUNK * 24];

    int t   = threadIdx.x;
    int co  = t % 24;
    int ohl = t / 24;
    int tiles = tps * tps;
    int n  = blockIdx.x / tiles;
    int tl = blockIdx.x % tiles;
    int oh0 = (tl / tps) * 8;
    int ow0 = (tl % tps) * 8;

    float acc[8];
#pragma unroll
    for (int i = 0; i < 8; i++) acc[i] = 0.f;

    for (int cc = 0; cc < CIN; cc += CHUNK) {
        __syncthreads();
        for (int l = t; l < CHUNK * 289; l += 192) {
            int ci  = l / 289;
            int rem = l % 289;
            int r = rem / 17, c = rem % 17;
            int ih = oh0 * 2 - 1 + r;
            int iw = ow0 * 2 - 1 + c;
            float v = 0.f;
            if (ih >= 0 && ih < Hin && iw >= 0 && iw < Hin)
                v = in[((n * CIN + cc + ci) * Hin + ih) * Hin + iw];
            in_s[l] = v;
        }
        for (int l = t; l < 9 * CHUNK * 24; l += 192) {
            int kk  = l / (CHUNK * 24);
            int rem = l % (CHUNK * 24);
            int ci = rem / 24, c2 = rem % 24;
            w_s[l] = w[(kk * CIN + cc + ci) * 24 + c2];
        }
        __syncthreads();

#pragma unroll
        for (int kh = 0; kh < 3; kh++)
#pragma unroll
            for (int kw = 0; kw < 3; kw++)
                for (int ci = 0; ci < CHUNK; ci++) {
                    float wv = w_s[(kh * 3 + kw) * CHUNK * 24 + ci * 24 + co];
                    const float* ir = &in_s[ci * 289 + (ohl * 2 + kh) * 17 + kw];
#pragma unroll
                    for (int o = 0; o < 8; o++)
                        acc[o] += wv * ir[o * 2];
                }
    }

    float sc = bns[co], bb = bnb[co];
#pragma unroll
    for (int o = 0; o < 8; o++) {
        float v = fmaxf(acc[o] * sc + bb, 0.f);
        out[((n * 24 + co) * Hout + oh0 + ohl) * Hout + ow0 + o] = v;
    }
}

// ---------------------------------------------------------------------------
// g layer 1 (unchanged)
// ---------------------------------------------------------------------------
__global__ void __launch_bounds__(256) g1_kernel(
    const float* __restrict__ c3, const float* __restrict__ qst,
    const float* __restrict__ gw1, const float* __restrict__ gb1,
    float* __restrict__ hi, float* __restrict__ hj)
{
    __shared__ float xs[64 * 26];
    __shared__ float qs[128];
    int n = blockIdx.x, t = threadIdx.x;

    for (int l = t; l < 64 * 26; l += 256) {
        int p = l / 26, c = l % 26;
        int h = p >> 3, w = p & 7;
        float v;
        if (c < 24)       v = c3[((n * 24 + c) * 8 + h) * 8 + w];
        else if (c == 24) v = -1.f + (2.f / 7.f) * (float)w;
        else              v = -1.f + (2.f / 7.f) * (float)h;
        xs[l] = v;
    }
    if (t < 128) qs[t] = qst[n * 128 + t];
    __syncthreads();

    int o = t;
    float wa[26], wb[26];
#pragma unroll
    for (int c = 0; c < 26; c++) {
        wa[c] = gw1[c * 256 + o];
        wb[c] = gw1[(26 + c) * 256 + o];
    }
    float hq = gb1[o];
    for (int k = 0; k < 128; k++) hq += qs[k] * gw1[(52 + k) * 256 + o];

    for (int p = 0; p < 64; p++) {
        float ai = hq, bj = 0.f;
#pragma unroll
        for (int c = 0; c < 26; c++) {
            float x = xs[p * 26 + c];
            ai += x * wa[c];
            bj += x * wb[c];
        }
        hi[(n * 64 + p) * 256 + o] = ai;
        hj[(n * 64 + p) * 256 + o] = bj;
    }
}

// ---------------------------------------------------------------------------
// Weight prep: W[k][n] fp32 -> fragment-ordered bf16 hi/lo blob.
// Blob: 24 chunks (3 layers x 8 k-chunks of 32), each chunk = hi slab (16KB)
// + lo slab (16KB). Slab layout: [n(256)][16 words], word pos encodes the
// interleaved (b0,b1) pairing:
//   k2c = (k>>1)&15, s = k2c>>3, wi = k2c&7
//   pos = s*8 + (wi<4 ? wi*2 : (wi-4)*2+1); ushort slot = pos*2 + (k&1)
// ---------------------------------------------------------------------------
__global__ void __launch_bounds__(256) prep_w_kernel(
    const float* __restrict__ w2, const float* __restrict__ w3,
    const float* __restrict__ w4, unsigned short* __restrict__ blob)
{
    int idx = blockIdx.x * 256 + threadIdx.x;      // 0..196607
    int l = idx >> 16;
    int rem = idx & 65535;
    int k = rem >> 8, n = rem & 255;
    const float* W = (l == 0) ? w2 : ((l == 1) ? w3 : w4);
    float w = W[k * 256 + n];
    __nv_bfloat16 wh = __float2bfloat16(w);
    __nv_bfloat16 wl = __float2bfloat16(w - __bfloat162float(wh));

    int c   = k >> 5;                 // k-chunk within layer
    int k2c = (k >> 1) & 15;
    int s   = k2c >> 3;
    int wi  = k2c & 7;
    int pos = s * 8 + ((wi < 4) ? (wi * 2) : ((wi - 4) * 2 + 1));
    int gc  = l * 8 + c;
    // slabs in ushorts: each slab 8192 ushorts
    unsigned short hv = *(unsigned short*)&wh;
    unsigned short lv = *(unsigned short*)&wl;
    blob[(size_t)(gc * 2 + 0) * 8192 + (n * 16 + pos) * 2 + (k & 1)] = hv;
    blob[(size_t)(gc * 2 + 1) * 8192 + (n * 16 + pos) * 2 + (k & 1)] = lv;
}

// ---------------------------------------------------------------------------
// mma.sync relation MLP.
// Block = 128 pairs (2 i x 64 j), 256 threads = 8 warps (wm 0..3 over M,
// wn 0..1 over N halves). A in SMEM as bf16 hi/lo, row stride 132 words.
// Weights streamed per 32-k chunk (hi+lo 32KB) via cp.async double buffer.
// SMEM words: Ah[0,16896) Al[16896,33792) W[33792,54272) bias[54272,55040)
//             red[55040,56064)  -> 224256 bytes
// ---------------------------------------------------------------------------
extern __shared__ uint32_t smw[];

__device__ __forceinline__ void issue_chunk(const char* __restrict__ blob,
                                            uint32_t wsm, int gc, int tid)
{
    const char* src = blob + (size_t)gc * 32768;
#pragma unroll
    for (int r = 0; r < 8; r++) {
        int op = r * 256 + tid;          // 0..2047
        int h = op >> 10, e = op & 1023, n = e >> 2, v = e & 3;
        uint32_t dst = wsm + (uint32_t)(h * 20480 + n * 80 + v * 16);
        CP_ASYNC16(dst, src + h * 16384 + n * 64 + v * 16);
    }
    CP_COMMIT();
}

__global__ void __launch_bounds__(256) rn_g_mma(
    const float* __restrict__ hi, const float* __restrict__ hj,
    const unsigned short* __restrict__ wblob,
    const float* __restrict__ b2, const float* __restrict__ b3,
    const float* __restrict__ b4, float* __restrict__ spart)
{
    const char* blob = (const char*)wblob;
    int tid = threadIdx.x;
    int wid = tid >> 5, lane = tid & 31;
    int g = lane >> 2, t = lane & 3;
    int wm = wid & 3, wn = wid >> 2;

    float* biasf = (float*)&smw[54272];
    float* red   = (float*)&smw[55040];
    uint32_t sb = smem_u32(smw);
    uint32_t wsm0 = sb + 135168u;          // buf0 bytes
    uint32_t wsm1 = sb + 135168u + 40960u; // buf1

    biasf[tid]       = b2[tid];
    biasf[256 + tid] = b3[tid];
    biasf[512 + tid] = b4[tid];

    // prologue: chunk 0 -> buf0
    issue_chunk(blob, wsm0, 0, tid);

    // ---- L0: A = relu(hi_i + hj_j), split bf16 hi/lo into smem
    int nb  = blockIdx.x >> 5;
    int ip  = blockIdx.x & 31;
    {
        int m = tid >> 1, kh = tid & 1;
        const float* hir = hi + (size_t)(nb * 64 + ip * 2 + (m >> 6)) * 256 + kh * 128;
        const float* hjr = hj + (size_t)(nb * 64 + (m & 63)) * 256 + kh * 128;
        int base = m * 132 + kh * 64;
#pragma unroll 4
        for (int w = 0; w < 64; w++) {
            float2 a = *(const float2*)(hir + 2 * w);
            float2 b = *(const float2*)(hjr + 2 * w);
            float v0 = fmaxf(a.x + b.x, 0.f);
            float v1 = fmaxf(a.y + b.y, 0.f);
            uint32_t aw = packbf(v0, v1);
            float l0 = v0 - bfLO(aw), l1 = v1 - bfHI(aw);
            smw[base + w] = aw;
            smw[16896 + base + w] = packbf(l0, l1);
        }
    }

    float acc[2][16][4];

    // precomputed row bases (words) for A fragments
    int rb[4];
#pragma unroll
    for (int r = 0; r < 4; r++) rb[r] = (wm * 32 + g + r * 8) * 132;

#pragma unroll 1
    for (int l = 0; l < 3; l++) {
#pragma unroll
        for (int mt = 0; mt < 2; mt++)
#pragma unroll
            for (int nt = 0; nt < 16; nt++)
#pragma unroll
                for (int q = 0; q < 4; q++) acc[mt][nt][q] = 0.f;

#pragma unroll 1
        for (int c = 0; c < 8; c++) {
            int gc = l * 8 + c;
            if (gc < 23)
                issue_chunk(blob, (gc & 1) ? wsm0 : wsm1, gc + 1, tid);  // gc+1 -> buf (gc+1)&1
            if (gc < 23) asm volatile("cp.async.wait_group 1;" ::: "memory");
            else         asm volatile("cp.async.wait_group 0;" ::: "memory");
            __syncthreads();

            uint32_t wb = 33792u + (uint32_t)(c & 1) * 10240u;  // word idx of hi slab
#pragma unroll
            for (int s = 0; s < 2; s++) {
                int ks8 = (c * 2 + s) * 8;
                uint32_t ah[2][4], al[2][4];
#pragma unroll
                for (int mt = 0; mt < 2; mt++) {
                    ah[mt][0] = smw[rb[mt * 2]     + ks8 + t];
                    ah[mt][1] = smw[rb[mt * 2 + 1] + ks8 + t];
                    ah[mt][2] = smw[rb[mt * 2]     + ks8 + t + 4];
                    ah[mt][3] = smw[rb[mt * 2 + 1] + ks8 + t + 4];
                    al[mt][0] = smw[16896 + rb[mt * 2]     + ks8 + t];
                    al[mt][1] = smw[16896 + rb[mt * 2 + 1] + ks8 + t];
                    al[mt][2] = smw[16896 + rb[mt * 2]     + ks8 + t + 4];
                    al[mt][3] = smw[16896 + rb[mt * 2 + 1] + ks8 + t + 4];
                }
#pragma unroll
                for (int nt = 0; nt < 16; nt++) {
                    uint32_t nw = (uint32_t)((wn * 128 + nt * 8 + g) * 20 + s * 8 + 2 * t);
                    uint2 bh = *(const uint2*)&smw[wb + nw];
                    uint2 bl = *(const uint2*)&smw[wb + 5120 + nw];
#pragma unroll
                    for (int mt = 0; mt < 2; mt++) {
                        mma_bf16(acc[mt][nt][0], acc[mt][nt][1], acc[mt][nt][2], acc[mt][nt][3],
                                 ah[mt][0], ah[mt][1], ah[mt][2], ah[mt][3], bh.x, bh.y);
                        mma_bf16(acc[mt][nt][0], acc[mt][nt][1], acc[mt][nt][2], acc[mt][nt][3],
                                 al[mt][0], al[mt][1], al[mt][2], al[mt][3], bh.x, bh.y);
                        mma_bf16(acc[mt][nt][0], acc[mt][nt][1], acc[mt][nt][2], acc[mt][nt][3],
                                 ah[mt][0], ah[mt][1], ah[mt][2], ah[mt][3], bl.x, bl.y);
                    }
                }
            }
            __syncthreads();
        }

        if (l < 2) {
            // epilogue: relu(acc + bias) -> split bf16 -> A smem
#pragma unroll
            for (int mt = 0; mt < 2; mt++)
#pragma unroll
                for (int nt = 0; nt < 16; nt++) {
                    int n0 = wn * 128 + nt * 8 + 2 * t;
                    float2 bv = *(const float2*)&biasf[l * 256 + n0];
                    int nh = n0 >> 1;
                    // row g
                    {
                        float v0 = fmaxf(acc[mt][nt][0] + bv.x, 0.f);
                        float v1 = fmaxf(acc[mt][nt][1] + bv.y, 0.f);
                        uint32_t aw = packbf(v0, v1);
                        float l0 = v0 - bfLO(aw), l1 = v1 - bfHI(aw);
                        int rw = (wm * 32 + mt * 16 + g) * 132 + nh;
                        smw[rw] = aw;
                        smw[16896 + rw] = packbf(l0, l1);
                    }
                    // row g+8
                    {
                        float v0 = fmaxf(acc[mt][nt][2] + bv.x, 0.f);
                        float v1 = fmaxf(acc[mt][nt][3] + bv.y, 0.f);
                        uint32_t aw = packbf(v0, v1);
                        float l0 = v0 - bfLO(aw), l1 = v1 - bfHI(aw);
                        int rw = (wm * 32 + mt * 16 + g + 8) * 132 + nh;
                        smw[rw] = aw;
                        smw[16896 + rw] = packbf(l0, l1);
                    }
                }
            // next layer's first __syncthreads orders these writes vs reads
        } else {
            // final layer: relu + bias, column-sum over m
#pragma unroll
            for (int nt = 0; nt < 16; nt++) {
                int n0 = wn * 128 + nt * 8 + 2 * t;
                float2 bv = *(const float2*)&biasf[512 + n0];
                float cs0 = fmaxf(acc[0][nt][0] + bv.x, 0.f) + fmaxf(acc[0][nt][2] + bv.x, 0.f)
                          + fmaxf(acc[1][nt][0] + bv.x, 0.f) + fmaxf(acc[1][nt][2] + bv.x, 0.f);
                float cs1 = fmaxf(acc[0][nt][1] + bv.y, 0.f) + fmaxf(acc[0][nt][3] + bv.y, 0.f)
                          + fmaxf(acc[1][nt][1] + bv.y, 0.f) + fmaxf(acc[1][nt][3] + bv.y, 0.f);
#pragma unroll
                for (int off = 16; off >= 4; off >>= 1) {
                    cs0 += __shfl_xor_sync(0xffffffffu, cs0, off);
                    cs1 += __shfl_xor_sync(0xffffffffu, cs1, off);
                }
                if (g == 0) {
                    red[wm * 256 + n0] = cs0;
                    red[wm * 256 + n0 + 1] = cs1;
                }
            }
            __syncthreads();
            float s = red[tid] + red[256 + tid] + red[512 + tid] + red[768 + tid];
            spart[(size_t)blockIdx.x * 256 + tid] = s;
        }
    }
}

// ---------------------------------------------------------------------------
// Reduce 32 partials per n, f-MLP + classifier + log_softmax
// ---------------------------------------------------------------------------
__global__ void __launch_bounds__(256) f_kernel(
    const float* __restrict__ spart,
    const float* __restrict__ fw1, const float* __restrict__ fb1,
    const float* __restrict__ fw2, const float* __restrict__ fb2,
    const float* __restrict__ cw,  const float* __restrict__ cb,
    float* __restrict__ out)
{
    __shared__ float a[256], b[256];
    int n = blockIdx.x, t = threadIdx.x;

    const float* sp = spart + (size_t)(n * 32) * 256 + t;
    float v = 0.f;
    for (int i = 0; i < 32; i++) v += sp[i * 256];
    a[t] = v;
    __syncthreads();

    float acc = fb1[t];
    for (int k = 0; k < 256; k++) acc += a[k] * fw1[k * 256 + t];
    acc = fmaxf(acc, 0.f);
    b[t] = acc;
    __syncthreads();

    acc = fb2[t];
    for (int k = 0; k < 256; k++) acc += b[k] * fw2[k * 256 + t];
    acc = fmaxf(acc, 0.f);
    a[t] = acc;
    __syncthreads();

    if (t < 32) {
        float lg = cb[t];
        for (int k = 0; k < 256; k++) lg += a[k] * cw[k * 32 + t];
        float mx = lg;
#pragma unroll
        for (int off = 16; off; off >>= 1)
            mx = fmaxf(mx, __shfl_xor_sync(0xffffffffu, mx, off));
        float e = expf(lg - mx);
        float se = e;
#pragma unroll
        for (int off = 16; off; off >>= 1)
            se += __shfl_xor_sync(0xffffffffu, se, off);
        out[(n << 5) + t] = lg - mx - logf(se);
    }
}

// ---------------------------------------------------------------------------
// Launch
// ---------------------------------------------------------------------------
extern "C" void kernel_launch(void* const* d_in, const int* in_sizes, int n_in,
                              void* d_out, int out_size)
{
    const float* img  = (const float*)d_in[0];
    const float* qst  = (const float*)d_in[1];
    const float* cw0  = (const float*)d_in[2];
    const float* cw1  = (const float*)d_in[3];
    const float* cw2  = (const float*)d_in[4];
    const float* cw3  = (const float*)d_in[5];
    const float* bs0  = (const float*)d_in[6];
    const float* bb0  = (const float*)d_in[7];
    const float* bs1  = (const float*)d_in[8];
    const float* bb1  = (const float*)d_in[9];
    const float* bs2  = (const float*)d_in[10];
    const float* bb2  = (const float*)d_in[11];
    const float* bs3  = (const float*)d_in[12];
    const float* bb3  = (const float*)d_in[13];
    const float* gw1  = (const float*)d_in[14];
    const float* gb1  = (const float*)d_in[15];
    const float* gw2  = (const float*)d_in[16];
    const float* gb2  = (const float*)d_in[17];
    const float* gw3  = (const float*)d_in[18];
    const float* gb3  = (const float*)d_in[19];
    const float* gw4  = (const float*)d_in[20];
    const float* gb4  = (const float*)d_in[21];
    const float* fw1  = (const float*)d_in[22];
    const float* fb1  = (const float*)d_in[23];
    const float* fw2  = (const float*)d_in[24];
    const float* fb2  = (const float*)d_in[25];
    const float* clw  = (const float*)d_in[26];
    const float* clb  = (const float*)d_in[27];
    float* out = (float*)d_out;

    void* base_v = nullptr;
    cudaGetSymbolAddress(&base_v, g_scratch);
    float* base = (float*)base_v;
    float* c0 = base + C0_OFF;
    float* c1 = base + C1_OFF;
    float* c2 = base + C2_OFF;
    float* c3 = base + C3_OFF;
    float* hi = base + HI_OFF;
    float* hj = base + HJ_OFF;
    float* sp = base + SP_OFF;
    unsigned short* wp = (unsigned short*)(base + WP_OFF);

    cudaFuncSetAttribute(rn_g_mma, cudaFuncAttributeMaxDynamicSharedMemorySize, 224256);

    prep_w_kernel<<<768, 256>>>(gw2, gw3, gw4, wp);

    conv_bn_relu_kernel<3, 3><<<4096, 192>>>(img, cw0, bs0, bb0, c0, 128, 64, 8);
    conv_bn_relu_kernel<24, 12><<<1024, 192>>>(c0, cw1, bs1, bb1, c1, 64, 32, 4);
    conv_bn_relu_kernel<24, 12><<<256, 192>>>(c1, cw2, bs2, bb2, c2, 32, 16, 2);
    conv_bn_relu_kernel<24, 12><<<64, 192>>>(c2, cw3, bs3, bb3, c3, 16, 8, 1);

    g1_kernel<<<64, 256>>>(c3, qst, gw1, gb1, hi, hj);

    rn_g_mma<<<2048, 256, 224256>>>(hi, hj, wp, gb2, gb3, gb4, sp);

    f_kernel<<<64, 256>>>(sp, fw1, fb1, fw2, fb2, clw, clb, out);
}

// round 4
// speedup vs baseline: 4.4326x; 1.3632x over previous
#include <cuda_runtime.h>
#include <cuda_fp16.h>
#include <math.h>
#include <cstdint>

// ---------------------------------------------------------------------------
// Scratch
// ---------------------------------------------------------------------------
#define C0_OFF   0u
#define C1_OFF   6291456u
#define C2_OFF   7864320u
#define C3_OFF   8257536u
#define HI_OFF   8355840u
#define HJ_OFF   9404416u
#define SP_OFF   10452992u                // 4096*256 floats
#define WP_OFF   11501568u                // fp16 blob: 24*8192 ushorts = 384KB
#define SCRATCH_TOTAL 11698176u

__device__ float g_scratch[SCRATCH_TOTAL];

// ---------------------------------------------------------------------------
// Helpers
// ---------------------------------------------------------------------------
__device__ __forceinline__ uint32_t smem_u32(const void* p) {
    uint32_t a;
    asm("{ .reg .u64 t; cvta.to.shared.u64 t, %1; cvt.u32.u64 %0, t; }" : "=r"(a) : "l"(p));
    return a;
}

__device__ __forceinline__ void mma_f16(float& d0, float& d1, float& d2, float& d3,
                                        uint32_t a0, uint32_t a1, uint32_t a2, uint32_t a3,
                                        uint32_t b0, uint32_t b1) {
    asm volatile(
        "mma.sync.aligned.m16n8k16.row.col.f32.f16.f16.f32 "
        "{%0,%1,%2,%3},{%4,%5,%6,%7},{%8,%9},{%0,%1,%2,%3};"
        : "+f"(d0), "+f"(d1), "+f"(d2), "+f"(d3)
        : "r"(a0), "r"(a1), "r"(a2), "r"(a3), "r"(b0), "r"(b1));
}

// pack: low half = f16(v0), high half = f16(v1)
__device__ __forceinline__ uint32_t packh(float v0, float v1) {
    uint32_t r;
    asm("cvt.rn.f16x2.f32 %0, %1, %2;" : "=r"(r) : "f"(v1), "f"(v0));
    return r;
}

#define CP_ASYNC16(dst, src) \
    asm volatile("cp.async.cg.shared.global [%0], [%1], 16;" :: "r"(dst), "l"(src) : "memory")
#define CP_COMMIT() asm volatile("cp.async.commit_group;" ::: "memory")

// ---------------------------------------------------------------------------
// Conv + BN + ReLU, row-cached inner loop (pad rows to 18 floats, LDS.64)
// ---------------------------------------------------------------------------
template<int CIN, int CHUNK>
__global__ void __launch_bounds__(192) conv_bn_relu_kernel(
    const float* __restrict__ in, const float* __restrict__ w,
    const float* __restrict__ bns, const float* __restrict__ bnb,
    float* __restrict__ out, int Hin, int Hout, int tps)
{
    __shared__ float in_s[CHUNK * 306];      // CHUNK x 17 rows x 18 cols (col 17 pad)
    __shared__ float w_s[9 * CHUNK * 24];

    int t   = threadIdx.x;
    int co  = t % 24;
    int ohl = t / 24;
    int tiles = tps * tps;
    int n  = blockIdx.x / tiles;
    int tl = blockIdx.x % tiles;
    int oh0 = (tl / tps) * 8;
    int ow0 = (tl % tps) * 8;

    float acc[8];
#pragma unroll
    for (int i = 0; i < 8; i++) acc[i] = 0.f;

    for (int cc = 0; cc < CIN; cc += CHUNK) {
        __syncthreads();
        for (int l = t; l < CHUNK * 306; l += 192) {
            int ci  = l / 306;
            int rem = l % 306;
            int r = rem / 18, c = rem % 18;
            float v = 0.f;
            if (c < 17) {
                int ih = oh0 * 2 - 1 + r;
                int iw = ow0 * 2 - 1 + c;
                if (ih >= 0 && ih < Hin && iw >= 0 && iw < Hin)
                    v = in[((n * CIN + cc + ci) * Hin + ih) * Hin + iw];
            }
            in_s[l] = v;
        }
        for (int l = t; l < 9 * CHUNK * 24; l += 192) {
            int kk  = l / (CHUNK * 24);
            int rem = l % (CHUNK * 24);
            int ci = rem / 24, c2 = rem % 24;
            w_s[l] = w[(kk * CIN + cc + ci) * 24 + c2];
        }
        __syncthreads();

        for (int ci = 0; ci < CHUNK; ci++) {
            float wr[9];
#pragma unroll
            for (int kk = 0; kk < 9; kk++)
                wr[kk] = w_s[kk * CHUNK * 24 + ci * 24 + co];
#pragma unroll
            for (int r = 0; r < 3; r++) {
                const float2* ip = (const float2*)&in_s[ci * 306 + (ohl * 2 + r) * 18];
                float2 f[9];
#pragma unroll
                for (int j = 0; j < 9; j++) f[j] = ip[j];
#pragma unroll
                for (int o = 0; o < 8; o++) {
                    acc[o] += wr[r * 3 + 0] * f[o].x;
                    acc[o] += wr[r * 3 + 1] * f[o].y;
                    acc[o] += wr[r * 3 + 2] * f[o + 1].x;
                }
            }
        }
    }

    float sc = bns[co], bb = bnb[co];
#pragma unroll
    for (int o = 0; o < 8; o++) {
        float v = fmaxf(acc[o] * sc + bb, 0.f);
        out[((n * 24 + co) * Hout + oh0 + ohl) * Hout + ow0 + o] = v;
    }
}

// ---------------------------------------------------------------------------
// g layer 1: grid 256 (4 blocks per n, 16 p rows each)
// ---------------------------------------------------------------------------
__global__ void __launch_bounds__(256) g1_kernel(
    const float* __restrict__ c3, const float* __restrict__ qst,
    const float* __restrict__ gw1, const float* __restrict__ gb1,
    float* __restrict__ hi, float* __restrict__ hj)
{
    __shared__ float xs[64 * 26];
    __shared__ float qs[128];
    int n = blockIdx.x >> 2, pg = blockIdx.x & 3;
    int t = threadIdx.x;

    for (int l = t; l < 64 * 26; l += 256) {
        int p = l / 26, c = l % 26;
        int h = p >> 3, w = p & 7;
        float v;
        if (c < 24)       v = c3[((n * 24 + c) * 8 + h) * 8 + w];
        else if (c == 24) v = -1.f + (2.f / 7.f) * (float)w;
        else              v = -1.f + (2.f / 7.f) * (float)h;
        xs[l] = v;
    }
    if (t < 128) qs[t] = qst[n * 128 + t];
    __syncthreads();

    int o = t;
    float wa[26], wb[26];
#pragma unroll
    for (int c = 0; c < 26; c++) {
        wa[c] = gw1[c * 256 + o];
        wb[c] = gw1[(26 + c) * 256 + o];
    }
    float hq = gb1[o];
    for (int k = 0; k < 128; k++) hq += qs[k] * gw1[(52 + k) * 256 + o];

    for (int p = pg * 16; p < pg * 16 + 16; p++) {
        float ai = hq, bj = 0.f;
#pragma unroll
        for (int c = 0; c < 26; c++) {
            float x = xs[p * 26 + c];
            ai += x * wa[c];
            bj += x * wb[c];
        }
        hi[(n * 64 + p) * 256 + o] = ai;
        hj[(n * 64 + p) * 256 + o] = bj;
    }
}

// ---------------------------------------------------------------------------
// Weight prep: W[k][n] fp32 -> fragment-ordered fp16 blob.
// 24 chunks (3 layers x 8 k-chunks of 32), 16KB each.
// ushort slot within chunk: (n*16 + pos)*2 + (k&1), pos pairs (t, t+4).
// ---------------------------------------------------------------------------
__global__ void __launch_bounds__(256) prep_w_kernel(
    const float* __restrict__ w2, const float* __restrict__ w3,
    const float* __restrict__ w4, unsigned short* __restrict__ blob)
{
    int idx = blockIdx.x * 256 + threadIdx.x;      // 0..196607
    int l = idx >> 16;
    int rem = idx & 65535;
    int k = rem >> 8, n = rem & 255;
    const float* W = (l == 0) ? w2 : ((l == 1) ? w3 : w4);
    __half wh = __float2half(W[k * 256 + n]);

    int c   = k >> 5;
    int k2c = (k >> 1) & 15;
    int s   = k2c >> 3;
    int wi  = k2c & 7;
    int pos = s * 8 + ((wi < 4) ? (wi * 2) : ((wi - 4) * 2 + 1));
    int gc  = l * 8 + c;
    blob[(size_t)gc * 8192 + (n * 16 + pos) * 2 + (k & 1)] = *(unsigned short*)&wh;
}

// ---------------------------------------------------------------------------
// fp16 mma relation MLP. Block = 64 pairs (1 i x 64 j), 256 threads = 8 warps
// (wm 0..3 over 16-row M strips, wn 0..1 over N halves).
// SMEM words: A[0,8448) rows 64 x stride 132 (fp16x2)
//             WB0[8448,13568) WB1[13568,18688) (20 words per n: 16 + 4 pad)
//             bias[18688,19456) red[19456,20480)  -> 81920 bytes
// ---------------------------------------------------------------------------
extern __shared__ uint32_t smw[];

__device__ __forceinline__ void issue_chunk(const char* __restrict__ blob,
                                            uint32_t wsm, int gc, int tid)
{
    const char* src = blob + (size_t)gc * 16384;
#pragma unroll
    for (int r = 0; r < 4; r++) {
        int op = r * 256 + tid;          // 0..1023
        int n = op >> 2, v = op & 3;
        uint32_t dst = wsm + (uint32_t)(n * 80 + v * 16);
        CP_ASYNC16(dst, src + n * 64 + v * 16);
    }
    CP_COMMIT();
}

__global__ void __launch_bounds__(256) rn_g_mma(
    const float* __restrict__ hi, const float* __restrict__ hj,
    const unsigned short* __restrict__ wblob,
    const float* __restrict__ b2, const float* __restrict__ b3,
    const float* __restrict__ b4, float* __restrict__ spart)
{
    const char* blob = (const char*)wblob;
    int tid = threadIdx.x;
    int wid = tid >> 5, lane = tid & 31;
    int g = lane >> 2, t = lane & 3;
    int wm = wid & 3, wn = wid >> 2;

    float* biasf = (float*)&smw[18688];
    float* red   = (float*)&smw[19456];
    uint32_t sb = smem_u32(smw);
    uint32_t wsm0 = sb + 33792u;
    uint32_t wsm1 = sb + 54272u;

    biasf[tid]       = b2[tid];
    biasf[256 + tid] = b3[tid];
    biasf[512 + tid] = b4[tid];

    issue_chunk(blob, wsm0, 0, tid);

    // ---- L0: A = relu(hi_i + hj_j) as fp16x2
    int nb = blockIdx.x >> 6;
    int ii = blockIdx.x & 63;
    {
        int m = tid >> 2, q = tid & 3;
        const float* hir = hi + (size_t)(nb * 64 + ii) * 256 + q * 64;
        const float* hjr = hj + (size_t)(nb * 64 + m) * 256 + q * 64;
        int base = m * 132 + q * 32;
#pragma unroll 8
        for (int w = 0; w < 32; w++) {
            float2 a = *(const float2*)(hir + 2 * w);
            float2 b = *(const float2*)(hjr + 2 * w);
            smw[base + w] = packh(fmaxf(a.x + b.x, 0.f), fmaxf(a.y + b.y, 0.f));
        }
    }

    float acc[16][4];
    int rb0 = (wm * 16 + g) * 132;

#pragma unroll 1
    for (int l = 0; l < 3; l++) {
#pragma unroll
        for (int nt = 0; nt < 16; nt++)
#pragma unroll
            for (int q = 0; q < 4; q++) acc[nt][q] = 0.f;

#pragma unroll 1
        for (int c = 0; c < 8; c++) {
            int gc = l * 8 + c;
            if (gc < 23) {
                issue_chunk(blob, (gc & 1) ? wsm0 : wsm1, gc + 1, tid);
                asm volatile("cp.async.wait_group 1;" ::: "memory");
            } else {
                asm volatile("cp.async.wait_group 0;" ::: "memory");
            }
            __syncthreads();

            uint32_t wb = 8448u + (uint32_t)(gc & 1) * 5120u;   // word idx of W buffer
#pragma unroll
            for (int s = 0; s < 2; s++) {
                int ks8 = (c * 2 + s) * 8;
                uint32_t a0 = smw[rb0 + ks8 + t];
                uint32_t a1 = smw[rb0 + 1056 + ks8 + t];
                uint32_t a2 = smw[rb0 + ks8 + t + 4];
                uint32_t a3 = smw[rb0 + 1056 + ks8 + t + 4];
#pragma unroll
                for (int nt = 0; nt < 16; nt++) {
                    uint32_t nw = (uint32_t)((wn * 128 + nt * 8 + g) * 20 + s * 8 + 2 * t);
                    uint2 bh = *(const uint2*)&smw[wb + nw];
                    mma_f16(acc[nt][0], acc[nt][1], acc[nt][2], acc[nt][3],
                            a0, a1, a2, a3, bh.x, bh.y);
                }
            }
            __syncthreads();
        }

        if (l < 2) {
#pragma unroll
            for (int nt = 0; nt < 16; nt++) {
                int n0 = wn * 128 + nt * 8 + 2 * t;
                float2 bv = *(const float2*)&biasf[l * 256 + n0];
                int nh = n0 >> 1;
                smw[rb0 + nh] =
                    packh(fmaxf(acc[nt][0] + bv.x, 0.f), fmaxf(acc[nt][1] + bv.y, 0.f));
                smw[rb0 + 1056 + nh] =
                    packh(fmaxf(acc[nt][2] + bv.x, 0.f), fmaxf(acc[nt][3] + bv.y, 0.f));
            }
        } else {
#pragma unroll
            for (int nt = 0; nt < 16; nt++) {
                int n0 = wn * 128 + nt * 8 + 2 * t;
                float2 bv = *(const float2*)&biasf[512 + n0];
                float cs0 = fmaxf(acc[nt][0] + bv.x, 0.f) + fmaxf(acc[nt][2] + bv.x, 0.f);
                float cs1 = fmaxf(acc[nt][1] + bv.y, 0.f) + fmaxf(acc[nt][3] + bv.y, 0.f);
#pragma unroll
                for (int off = 16; off >= 4; off >>= 1) {
                    cs0 += __shfl_xor_sync(0xffffffffu, cs0, off);
                    cs1 += __shfl_xor_sync(0xffffffffu, cs1, off);
                }
                if (g == 0) {
                    red[wm * 256 + n0] = cs0;
                    red[wm * 256 + n0 + 1] = cs1;
                }
            }
            __syncthreads();
            float s = red[tid] + red[256 + tid] + red[512 + tid] + red[768 + tid];
            spart[(size_t)blockIdx.x * 256 + tid] = s;
        }
    }
}

// ---------------------------------------------------------------------------
// Reduce 64 partials per n, f-MLP + classifier + log_softmax
// ---------------------------------------------------------------------------
__global__ void __launch_bounds__(256) f_kernel(
    const float* __restrict__ spart,
    const float* __restrict__ fw1, const float* __restrict__ fb1,
    const float* __restrict__ fw2, const float* __restrict__ fb2,
    const float* __restrict__ cw,  const float* __restrict__ cb,
    float* __restrict__ out)
{
    __shared__ float a[256], b[256];
    int n = blockIdx.x, t = threadIdx.x;

    const float* sp = spart + (size_t)(n * 64) * 256 + t;
    float v = 0.f;
    for (int i = 0; i < 64; i++) v += sp[i * 256];
    a[t] = v;
    __syncthreads();

    float acc = fb1[t];
    for (int k = 0; k < 256; k++) acc += a[k] * fw1[k * 256 + t];
    acc = fmaxf(acc, 0.f);
    b[t] = acc;
    __syncthreads();

    acc = fb2[t];
    for (int k = 0; k < 256; k++) acc += b[k] * fw2[k * 256 + t];
    acc = fmaxf(acc, 0.f);
    a[t] = acc;
    __syncthreads();

    if (t < 32) {
        float lg = cb[t];
        for (int k = 0; k < 256; k++) lg += a[k] * cw[k * 32 + t];
        float mx = lg;
#pragma unroll
        for (int off = 16; off; off >>= 1)
            mx = fmaxf(mx, __shfl_xor_sync(0xffffffffu, mx, off));
        float e = expf(lg - mx);
        float se = e;
#pragma unroll
        for (int off = 16; off; off >>= 1)
            se += __shfl_xor_sync(0xffffffffu, se, off);
        out[(n << 5) + t] = lg - mx - logf(se);
    }
}

// ---------------------------------------------------------------------------
// Launch
// ---------------------------------------------------------------------------
extern "C" void kernel_launch(void* const* d_in, const int* in_sizes, int n_in,
                              void* d_out, int out_size)
{
    const float* img  = (const float*)d_in[0];
    const float* qst  = (const float*)d_in[1];
    const float* cw0  = (const float*)d_in[2];
    const float* cw1  = (const float*)d_in[3];
    const float* cw2  = (const float*)d_in[4];
    const float* cw3  = (const float*)d_in[5];
    const float* bs0  = (const float*)d_in[6];
    const float* bb0  = (const float*)d_in[7];
    const float* bs1  = (const float*)d_in[8];
    const float* bb1  = (const float*)d_in[9];
    const float* bs2  = (const float*)d_in[10];
    const float* bb2  = (const float*)d_in[11];
    const float* bs3  = (const float*)d_in[12];
    const float* bb3  = (const float*)d_in[13];
    const float* gw1  = (const float*)d_in[14];
    const float* gb1  = (const float*)d_in[15];
    const float* gw2  = (const float*)d_in[16];
    const float* gb2  = (const float*)d_in[17];
    const float* gw3  = (const float*)d_in[18];
    const float* gb3  = (const float*)d_in[19];
    const float* gw4  = (const float*)d_in[20];
    const float* gb4  = (const float*)d_in[21];
    const float* fw1  = (const float*)d_in[22];
    const float* fb1  = (const float*)d_in[23];
    const float* fw2  = (const float*)d_in[24];
    const float* fb2  = (const float*)d_in[25];
    const float* clw  = (const float*)d_in[26];
    const float* clb  = (const float*)d_in[27];
    float* out = (float*)d_out;

    void* base_v = nullptr;
    cudaGetSymbolAddress(&base_v, g_scratch);
    float* base = (float*)base_v;
    float* c0 = base + C0_OFF;
    float* c1 = base + C1_OFF;
    float* c2 = base + C2_OFF;
    float* c3 = base + C3_OFF;
    float* hi = base + HI_OFF;
    float* hj = base + HJ_OFF;
    float* sp = base + SP_OFF;
    unsigned short* wp = (unsigned short*)(base + WP_OFF);

    cudaFuncSetAttribute(rn_g_mma, cudaFuncAttributeMaxDynamicSharedMemorySize, 81920);

    prep_w_kernel<<<768, 256>>>(gw2, gw3, gw4, wp);

    conv_bn_relu_kernel<3, 3><<<4096, 192>>>(img, cw0, bs0, bb0, c0, 128, 64, 8);
    conv_bn_relu_kernel<24, 12><<<1024, 192>>>(c0, cw1, bs1, bb1, c1, 64, 32, 4);
    conv_bn_relu_kernel<24, 12><<<256, 192>>>(c1, cw2, bs2, bb2, c2, 32, 16, 2);
    conv_bn_relu_kernel<24, 12><<<64, 192>>>(c2, cw3, bs3, bb3, c3, 16, 8, 1);

    g1_kernel<<<256, 256>>>(c3, qst, gw1, gb1, hi, hj);

    rn_g_mma<<<4096, 256, 81920>>>(hi, hj, wp, gb2, gb3, gb4, sp);

    f_kernel<<<64, 256>>>(sp, fw1, fb1, fw2, fb2, clw, clb, out);
}